// round 2
// baseline (speedup 1.0000x reference)
#include <cuda_runtime.h>
#include <cstdint>

// QuantizedEmbedding: out[token, :] = dequant(weight[indices[token], :], scales[indices[token], :])
// weight: int32 per packed byte; even = trunc_div(w,16)-8 (high nibble), odd = (w & 15)-8 (low nibble)
// groupsize 32 floats = 16 packed values; scales per (row, group).
//
// R2: 128 threads/CTA, each thread handles two 8-packed segments (front/back half
// of the row) -> 4x LDG.128 + 2 scale loads issued up front (MLP=6), 8x STG.128,
// lane-contiguous addressing throughout. Streaming stores (evict-first).

static constexpr int PACKED   = 2048;   // packed int32 per row
static constexpr int NGROUPS  = 128;
static constexpr int DIM      = 4096;
static constexpr int THREADS  = 128;

__device__ __forceinline__ void unpack2(int w, float s, float& e, float& o) {
    int hi = w / 16;        // trunc toward zero, matches torch trunc div
    int lo = w & 15;        // nonnegative mod 16
    e = (float)(hi - 8) * s;
    o = (float)(lo - 8) * s;
}

__device__ __forceinline__ void dequant8(int4 w0, int4 w1, float s,
                                         float4& o0, float4& o1, float4& o2, float4& o3) {
    unpack2(w0.x, s, o0.x, o0.y);
    unpack2(w0.y, s, o0.z, o0.w);
    unpack2(w0.z, s, o1.x, o1.y);
    unpack2(w0.w, s, o1.z, o1.w);
    unpack2(w1.x, s, o2.x, o2.y);
    unpack2(w1.y, s, o2.z, o2.w);
    unpack2(w1.z, s, o3.x, o3.y);
    unpack2(w1.w, s, o3.z, o3.w);
}

__global__ void __launch_bounds__(THREADS)
qemb_kernel(const int* __restrict__ indices,
            const int* __restrict__ weight,
            const float* __restrict__ scales,
            float* __restrict__ out,
            int n_tokens)
{
    int token = blockIdx.x;
    if (token >= n_tokens) return;

    int idx = __ldg(indices + token);
    int t = threadIdx.x;

    const float* srow = scales + (long)idx * NGROUPS;
    const int4*  wrow = reinterpret_cast<const int4*>(weight + (long)idx * PACKED);

    // Segment A: packed [t*8, t*8+8)          -> group t>>1
    // Segment B: packed [1024 + t*8, +8)      -> group 64 + (t>>1)
    // Issue all 6 loads before any compute for MLP.
    float sA = __ldg(srow + (t >> 1));
    float sB = __ldg(srow + 64 + (t >> 1));
    int4 a0 = __ldg(wrow + t * 2);
    int4 a1 = __ldg(wrow + t * 2 + 1);
    int4 b0 = __ldg(wrow + 256 + t * 2);
    int4 b1 = __ldg(wrow + 256 + t * 2 + 1);

    float4 oa0, oa1, oa2, oa3, ob0, ob1, ob2, ob3;
    dequant8(a0, a1, sA, oa0, oa1, oa2, oa3);
    dequant8(b0, b1, sB, ob0, ob1, ob2, ob3);

    float4* orow = reinterpret_cast<float4*>(out + (long)token * DIM);
    // Segment A floats [t*16, t*16+16) -> float4 index t*4
    __stcs(orow + t * 4 + 0, oa0);
    __stcs(orow + t * 4 + 1, oa1);
    __stcs(orow + t * 4 + 2, oa2);
    __stcs(orow + t * 4 + 3, oa3);
    // Segment B floats [2048 + t*16, +16) -> float4 index 512 + t*4
    __stcs(orow + 512 + t * 4 + 0, ob0);
    __stcs(orow + 512 + t * 4 + 1, ob1);
    __stcs(orow + 512 + t * 4 + 2, ob2);
    __stcs(orow + 512 + t * 4 + 3, ob3);
}

extern "C" void kernel_launch(void* const* d_in, const int* in_sizes, int n_in,
                              void* d_out, int out_size)
{
    const int*   indices = (const int*)d_in[0];
    const int*   weight  = (const int*)d_in[1];
    const float* scales  = (const float*)d_in[2];
    float*       out     = (float*)d_out;

    int n_tokens = in_sizes[0];  // 4*4096 = 16384

    qemb_kernel<<<n_tokens, THREADS>>>(indices, weight, scales, out, n_tokens);
}